// round 15
// baseline (speedup 1.0000x reference)
#include <cuda_runtime.h>
#include <math.h>

#define HH 512
#define WW 512
#define BB 16
#define NPIX (HH*WW)
#define NTOT (BB*NPIX)
#define WPR 16            // 32-bit words per row
#define WPS (HH*WPR)      // words per sample bitmap = 8192

#define F_A  0.955f
#define F_B  1.3693f
#define BA_C (1.3693f - 0.955f)
#define F_INF 1e6f

// acc layout: 6 arrays of BB doubles
#define A_F    0
#define A_W0   16
#define A_W0D  32
#define A_I    48
#define A_P    64
#define A_T    80
#define ACC_N  96

#define DT_GRID_X 64              // 8 rows per block
#define DT_BLOCKS (DT_GRID_X * BB)

// Scratch (device globals; zero-initialized at load, self-reset each launch)
__device__ unsigned g_mbits[BB*WPS];     // mask bitmap
__device__ unsigned g_bbits[BB*WPS];     // boundary bitmap
__device__ int      g_maxdi[BB];         // per-sample max dist (float bits, >=0)
__device__ int      g_hasfg[BB];
__device__ int      g_hasb[BB];
__device__ int      g_anyzero[BB];
__device__ double   g_acc[ACC_N];
__device__ unsigned g_done;              // last-block counter (self-wrapping)

// ---------------------------------------------------------------------------
// Fused pack + boundary (unchanged).
__global__ void __launch_bounds__(256) packbound_kernel(const int* __restrict__ tgt) {
    int b = blockIdx.y;
    int r0 = blockIdx.x * 32;
    __shared__ unsigned pm[34 * WPR];

    for (int w = threadIdx.x; w < 34 * WPR; w += 256) {
        int ri = w >> 4;              // 0..33  -> row r0-1+ri
        int wi = w & 15;
        int y = r0 - 1 + ri;
        unsigned word = 0;
        if ((unsigned)y < (unsigned)HH) {
            const int4* T = (const int4*)(tgt + b * NPIX + y * WW + wi * 32);
            #pragma unroll
            for (int q = 0; q < 8; q++) {
                int4 v = T[q];
                word |= (v.x != 0 ? 1u : 0u) << (q*4 + 0);
                word |= (v.y != 0 ? 1u : 0u) << (q*4 + 1);
                word |= (v.z != 0 ? 1u : 0u) << (q*4 + 2);
                word |= (v.w != 0 ? 1u : 0u) << (q*4 + 3);
            }
        }
        pm[w] = word;
    }
    __syncthreads();

    int fg = 0, bd = 0, az = 0;
    #pragma unroll 1
    for (int w = threadIdx.x; w < 32 * WPR; w += 256) {
        int lr = (w >> 4) + 1;        // local row 1..32
        int wi = w & 15;
        int y = r0 + (w >> 4);
        unsigned any1 = 0, any0 = 0;
        #pragma unroll
        for (int dr = -1; dr <= 1; dr++) {
            int y2 = y + dr;
            if ((unsigned)y2 >= (unsigned)HH) continue;
            int l2 = lr + dr;
            unsigned c  = pm[l2 * WPR + wi];
            unsigned lw = (wi > 0)  ? pm[l2 * WPR + wi - 1] : 0u;
            unsigned rw = (wi < 15) ? pm[l2 * WPR + wi + 1] : 0u;
            any1 |= c | (c << 1) | (lw >> 31) | (c >> 1) | (rw << 31);
            unsigned cn = ~c;
            unsigned ln = (wi > 0)  ? ~lw : 0u;   // outside image votes nothing
            unsigned rn = (wi < 15) ? ~rw : 0u;
            any0 |= cn | (cn << 1) | (ln >> 31) | (cn >> 1) | (rn << 31);
        }
        unsigned bw = any1 & any0;
        unsigned mw = pm[lr * WPR + wi];
        g_bbits[b * WPS + y * WPR + wi] = bw;
        g_mbits[b * WPS + y * WPR + wi] = mw;
        fg |= (mw != 0u);
        bd |= (bw != 0u);
        az |= (mw != 0xffffffffu);
    }
    fg = __syncthreads_or(fg);
    bd = __syncthreads_or(bd);
    az = __syncthreads_or(az);
    if (threadIdx.x == 0) {
        if (fg) atomicOr(&g_hasfg[b], 1);
        if (bd) atomicOr(&g_hasb[b], 1);
        if (az) atomicOr(&g_anyzero[b], 1);
    }
}

// ---------------------------------------------------------------------------
// Distance (in columns) from x to nearest set bit in a 512-bit row.
// Seed word i = rw[i] ^ inv (inv selects boundary vs ~mask without staging).
__device__ __forceinline__ int nearest_bit(const unsigned* __restrict__ rw,
                                           unsigned inv, int x, int cap) {
    int wi = x >> 5, bi = x & 31;
    unsigned w = rw[wi] ^ inv;
    int d = 1 << 29;
    unsigned lm = w << (31 - bi);               // bits <= bi
    if (lm) d = __clz(lm);
    unsigned rm = w >> bi;                      // bits >= bi
    if (rm) d = min(d, __ffs(rm) - 1);
    #pragma unroll 1
    for (int k = 1; k < WPR; k++) {
        int lwi = wi - k, rwi = wi + k;
        int dl = (lwi >= 0)  ? (bi + 32*k - 31) : (1 << 29);
        int dr = (rwi < WPR) ? (32*k - bi)      : (1 << 29);
        if (min(dl, dr) >= min(d, cap)) break;
        if (lwi >= 0) {
            unsigned lw = rw[lwi] ^ inv;
            if (lw) d = min(d, bi + 32*k - 31 + __clz(lw));
        }
        if (rwi < WPR) {
            unsigned rw2 = rw[rwi] ^ inv;
            if (rw2) d = min(d, 32*k - bi + __ffs(rw2) - 1);
        }
    }
    return d;
}

// Cold path: full closed-form search when the pixel itself is not a seed.
__device__ __noinline__ float dt_search(const unsigned* __restrict__ sbase,
                                        unsigned inv, int y, int x) {
    float best = F_INF;
    int nd = nearest_bit(sbase + y * WPR, inv, x, 600);
    if (nd < (1 << 28)) best = F_A * (float)nd;
    #pragma unroll 1
    for (int dy = 1; dy < HH; dy++) {
        float ady = F_A * (float)dy;
        if (ady >= best) break;
        float capf = fmaxf((best - BA_C * (float)dy) * (1.0f / F_A),
                           fminf((float)dy, (best - ady) * (1.0f / BA_C))) + 1.0f;
        int cap = (int)fminf(capf, 600.0f);
        int yu = y - dy;
        if (yu >= 0) {
            int nd2 = nearest_bit(sbase + yu * WPR, inv, x, cap);
            if (nd2 < (1 << 28)) {
                float f = (nd2 >= dy) ? (F_A * (float)nd2 + BA_C * (float)dy)
                                      : (ady + BA_C * (float)nd2);
                best = fminf(best, f);
            }
        }
        int yd = y + dy;
        if (yd < HH) {
            int nd2 = nearest_bit(sbase + yd * WPR, inv, x, cap);
            if (nd2 < (1 << 28)) {
                float f = (nd2 >= dy) ? (F_A * (float)nd2 + BA_C * (float)dy)
                                      : (ady + BA_C * (float)nd2);
                best = fminf(best, f);
            }
        }
    }
    return best;
}

// ---------------------------------------------------------------------------
// Fused closed-form chamfer DT + loss + (last block) finalize + state reset.
// Each block: 8 rows; each thread: 8 consecutive pixels x 2 iterations.
// Split-by-class accumulation:
//   focal = 0.75*sum(v) - 0.5*sum_{t=1}(v),  v = om^2*bce
//   psum  = n1 + sum(om) - 2*sum_{t=1}(om)
//   inter = n1 - sum_{t=1}(om) ; tsum = n1 (popc)
// w0d/lmax updates only on non-seed pixels (seeds give best=0).
// pred uses SCALAR loads only (d_in not guaranteed 16B-aligned).
__global__ void __launch_bounds__(256) dtloss_kernel(const float* __restrict__ pred,
                                                     const float* __restrict__ lv,
                                                     float* __restrict__ out) {
    int b = blockIdx.y;
    int hb = g_hasb[b];
    const unsigned* ms = g_mbits + b * WPS;
    const unsigned* sbase = hb ? (g_bbits + b * WPS) : ms;
    const unsigned inv = hb ? 0u : 0xffffffffu;
    int hs = hb ? 1 : g_anyzero[b];

    int r0 = blockIdx.x * 8;
    float lmax = 0.0f;
    float vall = 0.f, vpos = 0.f, omall = 0.f, ompos = 0.f, w0d = 0.f;
    int n1 = 0;

    const int xg = (threadIdx.x & 63) * 8;     // 8-px chunk start in row
    const int ysub = threadIdx.x >> 6;         // 0..3

    #pragma unroll 1
    for (int it = 0; it < 2; it++) {
        int y = r0 + it * 4 + ysub;
        int wy = y * WPR + (xg >> 5);
        unsigned sw = sbase[wy] ^ inv;
        unsigned mw = ms[wy];
        int sh = xg & 31;                      // 0,8,16,24
        unsigned sbyte = (sw >> sh) & 0xFFu;
        unsigned mbyte = (mw >> sh) & 0xFFu;
        n1 += __popc(mbyte);

        const float* pp = pred + b * NPIX + y * WW + xg;
        float xs[8];
        #pragma unroll
        for (int k = 0; k < 8; k++) xs[k] = pp[k];

        #pragma unroll
        for (int k = 0; k < 8; k++) {
            int tb = (mbyte >> k) & 1u;
            float xv = xs[k];
            float u = tb ? -xv : xv;
            float e = __expf(-fabsf(xv));
            float g = 1.0f + e;
            float r = __fdividef(1.0f, g);
            float om = (u >= 0.0f) ? r : 1.0f - r;     // sigmoid(u) == w0
            float bce = fmaxf(u, 0.0f) + __logf(g);    // softplus(u)
            float v = om * om * bce;
            vall += v;
            omall += om;
            if (tb) { vpos += v; ompos += om; }
            if (!((sbyte >> k) & 1u)) {                // non-seed: rare
                float best = hs ? dt_search(sbase, inv, y, xg + k) : F_INF;
                lmax = fmaxf(lmax, best);
                w0d += om * best;
            }
        }
    }

    // assemble the 6 canonical sums (exact algebra; float rounding only)
    float fn1 = (float)n1;
    float a_f   = 0.75f * vall - 0.5f * vpos;
    float a_w0  = omall;
    float a_w0d = w0d;
    float a_i   = fn1 - ompos;
    float a_p   = fn1 + omall - 2.0f * ompos;
    float a_t   = fn1;

    // block reduce 6 sums + max
    #pragma unroll
    for (int o = 16; o > 0; o >>= 1) {
        a_f   += __shfl_down_sync(0xffffffffu, a_f,   o);
        a_w0  += __shfl_down_sync(0xffffffffu, a_w0,  o);
        a_w0d += __shfl_down_sync(0xffffffffu, a_w0d, o);
        a_i   += __shfl_down_sync(0xffffffffu, a_i,   o);
        a_p   += __shfl_down_sync(0xffffffffu, a_p,   o);
        a_t   += __shfl_down_sync(0xffffffffu, a_t,   o);
        lmax   = fmaxf(lmax, __shfl_down_sync(0xffffffffu, lmax, o));
    }
    __shared__ float red[8][7];
    int lane = threadIdx.x & 31, wid = threadIdx.x >> 5;
    if (lane == 0) {
        red[wid][0] = a_f;  red[wid][1] = a_w0; red[wid][2] = a_w0d;
        red[wid][3] = a_i;  red[wid][4] = a_p;  red[wid][5] = a_t;
        red[wid][6] = lmax;
    }
    __syncthreads();
    if (threadIdx.x == 0) {
        float s0=0, s1=0, s2=0, s3=0, s4=0, s5=0, m6=0;
        #pragma unroll
        for (int w = 0; w < 8; w++) {
            s0 += red[w][0]; s1 += red[w][1]; s2 += red[w][2];
            s3 += red[w][3]; s4 += red[w][4]; s5 += red[w][5];
            m6 = fmaxf(m6, red[w][6]);
        }
        atomicAdd(&g_acc[A_F + b],   (double)s0);
        atomicAdd(&g_acc[A_W0 + b],  (double)s1);
        atomicAdd(&g_acc[A_W0D + b], (double)s2);
        atomicAdd(&g_acc[A_I + b],   (double)s3);
        atomicAdd(&g_acc[A_P + b],   (double)s4);
        atomicAdd(&g_acc[A_T + b],   (double)s5);
        atomicMax(&g_maxdi[b], __float_as_int(m6));   // valid: m6 >= 0
    }

    // ---- last-block finalize (threadfence reduction idiom) ----
    __shared__ int isLast;
    __threadfence();
    if (threadIdx.x == 0) {
        unsigned n = atomicInc(&g_done, DT_BLOCKS - 1);   // wraps to 0 on last
        isLast = (n == DT_BLOCKS - 1);
    }
    __syncthreads();
    if (!isLast) return;

    // One warp: lane b (0..15) handles sample b; parallel loads hide latency.
    if (wid == 0) {
        double f_b = 0.0, bnd_b = 0.0, dice_b = 0.0, iou_b = 0.0;
        if (lane < BB) {
            int bb2 = lane;
            f_b = g_acc[A_F + bb2];
            double w0s  = g_acc[A_W0 + bb2];
            double w0ds = g_acc[A_W0D + bb2];
            if (g_hasfg[bb2]) {
                float mx = __int_as_float(g_maxdi[bb2]);
                double scale = (mx > 0.0f) ? 1.0 / fmax((double)mx, 1e-12) : 1.0;
                bnd_b = w0s + scale * w0ds;   // sum w0*(1 + d/mx)
            } else {
                bnd_b = 2.0 * w0s;            // dist == 1 everywhere
            }
            double inter = g_acc[A_I + bb2];
            double tot = g_acc[A_P + bb2] + g_acc[A_T + bb2];
            dice_b = (2.0 * inter + 1e-6) / (tot + 1e-6);
            iou_b  = (inter + 1e-6) / (tot - inter + 1e-6);
        }
        #pragma unroll
        for (int o = 8; o > 0; o >>= 1) {
            f_b    += __shfl_down_sync(0xffffffffu, f_b,    o);
            bnd_b  += __shfl_down_sync(0xffffffffu, bnd_b,  o);
            dice_b += __shfl_down_sync(0xffffffffu, dice_b, o);
            iou_b  += __shfl_down_sync(0xffffffffu, iou_b,  o);
        }
        if (lane == 0) {
            double N = (double)NTOT;
            double focal = f_b / N;
            double bnd   = bnd_b / N;
            double dice  = 1.0 - dice_b / (double)BB;
            double iou   = 1.0 - iou_b / (double)BB;
            float f = (float)focal, d = (float)dice, bo = (float)bnd, io = (float)iou;
            float total = expf(-lv[0]) * f + lv[0]
                        + expf(-lv[1]) * d + lv[1]
                        + expf(-lv[2]) * bo + lv[2]
                        + expf(-lv[3]) * io + lv[3];
            out[0] = total;
            out[1] = f;
            out[2] = d;
            out[3] = bo;
            out[4] = io;
        }
    }
    __syncthreads();
    // reset accumulator state for the next (deterministic) replay
    if (threadIdx.x < ACC_N) g_acc[threadIdx.x] = 0.0;
    if (threadIdx.x >= 128 && threadIdx.x < 128 + BB) {
        int t = threadIdx.x - 128;
        g_hasfg[t] = 0; g_hasb[t] = 0; g_anyzero[t] = 0; g_maxdi[t] = 0;
    }
}

// ---------------------------------------------------------------------------
extern "C" void kernel_launch(void* const* d_in, const int* in_sizes, int n_in,
                              void* d_out, int out_size) {
    const float* pred = (const float*)d_in[0];
    const int*   tgt  = (const int*)d_in[1];
    const float* lv   = (const float*)d_in[2];
    float* out = (float*)d_out;

    packbound_kernel<<<dim3(16, BB), 256>>>(tgt);
    dtloss_kernel<<<dim3(DT_GRID_X, BB), 256>>>(pred, lv, out);
}